// round 1
// baseline (speedup 1.0000x reference)
#include <cuda_runtime.h>

#define C   64
#define NX  64
#define NY  64
#define NZ  32
#define NVOX (NX*NY*NZ)   // 131072

// Projected separable tables: px[x][c], py[y][c], pz[z][c] (pz has bias and
// -2*p0 folded in). 16-byte aligned so we can read them as float4.
__device__ __align__(16) float g_px[NX * C];
__device__ __align__(16) float g_py[NY * C];
__device__ __align__(16) float g_pz[NZ * C];

// ---------------------------------------------------------------------------
// Pass 1: project the 160 basis rows of pe through W^T (+ fold b - 2*p0 into pz)
// pe layout [X, Y, Z, C] row-major:
//   pe[x,0,0,:] at x * (NY*NZ*C)
//   pe[0,y,0,:] at y * (NZ*C)
//   pe[0,0,z,:] at z * C
// Separability of the reference pe:
//   pe[x,y,z] = pe[x,0,0] + pe[0,y,0] + pe[0,0,z] - 2*pe[0,0,0]
// ---------------------------------------------------------------------------
__global__ void proj_kernel(const float* __restrict__ pe,
                            const float* __restrict__ W,
                            const float* __restrict__ b)
{
    __shared__ float sW[C * 65];   // padded stride 65 -> no bank conflicts
    __shared__ float row[C];
    __shared__ float row0[C];

    const int blk = blockIdx.x;
    const int c   = threadIdx.x;   // 64 threads

    // cooperative load of W [C,C] into padded smem
    for (int i = c; i < C * C; i += blockDim.x) {
        int r = i >> 6, k = i & 63;
        sW[r * 65 + k] = W[i];
    }

    const float* src;
    float* dst;
    bool is_z = false;
    if (blk < NX) {
        src = pe + (size_t)blk * (NY * NZ * C);
        dst = g_px + blk * C;
    } else if (blk < NX + NY) {
        int y = blk - NX;
        src = pe + (size_t)y * (NZ * C);
        dst = g_py + y * C;
    } else {
        int z = blk - NX - NY;
        src = pe + (size_t)z * C;
        dst = g_pz + z * C;
        is_z = true;
    }

    row[c]  = src[c];
    row0[c] = pe[c];     // pe[0,0,0,:]
    __syncthreads();

    float s = 0.f, s0 = 0.f;
    #pragma unroll
    for (int k = 0; k < C; ++k) {
        float w = sW[c * 65 + k];   // W[c,k]  (out[c] = sum_k pe[k] * W[c,k])
        s  += row[k]  * w;
        s0 += row0[k] * w;
    }
    if (is_z) s += b[c] - 2.f * s0;   // fold bias and -2*p0 into pz table
    dst[c] = s;
}

// ---------------------------------------------------------------------------
// Pass 2: out[b,n,c] = feat[b,n,c] + px[x][c] + py[y][c] + pz[z][c]
// Pure streaming add, float4-vectorized, tables in shared memory.
// ---------------------------------------------------------------------------
__global__ void __launch_bounds__(512)
add_kernel(const float4* __restrict__ feat,
           float4* __restrict__ out,
           unsigned total4)
{
    __shared__ float4 spx[NX * C / 4];   // 1024 float4 = 16 KB
    __shared__ float4 spy[NY * C / 4];   // 1024 float4 = 16 KB
    __shared__ float4 spz[NZ * C / 4];   //  512 float4 =  8 KB

    const float4* gpx = reinterpret_cast<const float4*>(g_px);
    const float4* gpy = reinterpret_cast<const float4*>(g_py);
    const float4* gpz = reinterpret_cast<const float4*>(g_pz);

    for (int i = threadIdx.x; i < NX * C / 4; i += 512) {
        spx[i] = gpx[i];
        spy[i] = gpy[i];
    }
    for (int i = threadIdx.x; i < NZ * C / 4; i += 512) {
        spz[i] = gpz[i];
    }
    __syncthreads();

    const unsigned stride = gridDim.x * blockDim.x;
    for (unsigned g = blockIdx.x * blockDim.x + threadIdx.x; g < total4; g += stride) {
        // 16 float4 per voxel row (C=64); batch is just a flat offset
        unsigned c4 = g & 15u;
        unsigned n  = (g >> 4) & (NVOX - 1u);
        unsigned x  = n >> 11;          // n / (NY*NZ)
        unsigned y  = (n >> 5) & 63u;   // (n / NZ) % NY
        unsigned z  = n & 31u;          // n % NZ

        float4 f = feat[g];
        float4 a = spx[(x << 4) | c4];
        float4 p = spy[(y << 4) | c4];
        float4 q = spz[(z << 4) | c4];

        float4 o;
        o.x = f.x + a.x + p.x + q.x;
        o.y = f.y + a.y + p.y + q.y;
        o.z = f.z + a.z + p.z + q.z;
        o.w = f.w + a.w + p.w + q.w;
        out[g] = o;
    }
}

extern "C" void kernel_launch(void* const* d_in, const int* in_sizes, int n_in,
                              void* d_out, int out_size)
{
    const float* feat = (const float*)d_in[0];  // [B, N, C]
    const float* pe   = (const float*)d_in[1];  // [X, Y, Z, C]
    const float* W    = (const float*)d_in[2];  // [C, C]
    const float* b    = (const float*)d_in[3];  // [C]

    proj_kernel<<<NX + NY + NZ, C>>>(pe, W, b);

    unsigned total4 = (unsigned)(out_size / 4);  // 16,777,216 float4
    add_kernel<<<592, 512>>>((const float4*)feat, (float4*)d_out, total4);
}

// round 2
// speedup vs baseline: 1.0397x; 1.0397x over previous
#include <cuda_runtime.h>

#define C    64
#define NX   64
#define NY   64
#define NZ   32
#define NVOX (NX*NY*NZ)      // 131072
#define NPOS (NVOX * (C/4))  // 2,097,152 float4 positions per batch plane
#define BATCH 8

// Projected separable tables: px[x][c], py[y][c], pz[z][c]
// (pz has bias and -2*proj(pe[0,0,0]) folded in). 16B aligned for float4.
__device__ __align__(16) float g_px[NX * C];
__device__ __align__(16) float g_py[NY * C];
__device__ __align__(16) float g_pz[NZ * C];

// ---------------------------------------------------------------------------
// Pass 1: project the 160 basis rows of pe through W^T.
// Separability of the reference pe (exact in fp32 up to rounding):
//   pe[x,y,z] = pe[x,0,0] + pe[0,y,0] + pe[0,0,z] - 2*pe[0,0,0]
// 10 blocks x 1024 threads; block handles 16 rows, one output per thread.
// ---------------------------------------------------------------------------
__global__ void __launch_bounds__(1024)
proj_kernel(const float* __restrict__ pe,
            const float* __restrict__ W,
            const float* __restrict__ b)
{
    __shared__ float sW[C * 65];   // padded: bank = (c+k)%32, conflict-free
    __shared__ float sR[16 * C];   // the 16 pe rows this block projects
    __shared__ float sR0[C];       // pe[0,0,0,:]

    const int tid  = threadIdx.x;
    const int rloc = tid >> 6;     // 0..15  local row
    const int c    = tid & 63;     // output channel

    // cooperative load of W [C,C]: 4 floats per thread
    #pragma unroll
    for (int i = tid; i < C * C; i += 1024)
        sW[(i >> 6) * 65 + (i & 63)] = W[i];

    const int row = blockIdx.x * 16 + rloc;   // 0..159
    const float* src;
    if (row < NX)            src = pe + (size_t)row * (NY * NZ * C);
    else if (row < NX + NY)  src = pe + (size_t)(row - NX) * (NZ * C);
    else                     src = pe + (size_t)(row - NX - NY) * C;

    sR[rloc * C + c] = src[c];
    if (tid < C) sR0[tid] = pe[tid];
    __syncthreads();

    float s = 0.f, s0 = 0.f;
    #pragma unroll
    for (int k = 0; k < C; ++k) {
        float w = sW[c * 65 + k];        // W[c,k]
        s  += sR[rloc * C + k] * w;
        s0 += sR0[k] * w;
    }

    if (row < NX) {
        g_px[row * C + c] = s;
    } else if (row < NX + NY) {
        g_py[(row - NX) * C + c] = s;
    } else {
        // fold bias and -2*proj(pe000) into the z table
        g_pz[(row - NX - NY) * C + c] = s + b[c] - 2.f * s0;
    }
}

// ---------------------------------------------------------------------------
// Pass 2: out[b,n,c] = feat[b,n,c] + (px[x]+py[y]+pz[z])[c]
// Each thread owns a (n, c4) position: compute the pe term ONCE, then stream
// the 8 batch planes -> 8 independent LDG.128 in flight, 8x less table math.
// ---------------------------------------------------------------------------
__global__ void __launch_bounds__(256)
add_kernel(const float4* __restrict__ feat,
           float4* __restrict__ out)
{
    const float4* __restrict__ px = reinterpret_cast<const float4*>(g_px);
    const float4* __restrict__ py = reinterpret_cast<const float4*>(g_py);
    const float4* __restrict__ pz = reinterpret_cast<const float4*>(g_pz);

    const unsigned stride = gridDim.x * blockDim.x;
    for (unsigned p = blockIdx.x * blockDim.x + threadIdx.x; p < NPOS; p += stride) {
        const unsigned c4 = p & 15u;           // float4 index within channel row
        const unsigned n  = p >> 4;
        const unsigned x  = n >> 11;           // n / (NY*NZ)
        const unsigned y  = (n >> 5) & 63u;    // (n / NZ) % NY
        const unsigned z  = n & 31u;           // n % NZ

        const float4 a = __ldg(&px[(x << 4) | c4]);
        const float4 u = __ldg(&py[(y << 4) | c4]);
        const float4 v = __ldg(&pz[(z << 4) | c4]);

        float4 t;
        t.x = a.x + u.x + v.x;
        t.y = a.y + u.y + v.y;
        t.z = a.z + u.z + v.z;
        t.w = a.w + u.w + v.w;

        #pragma unroll
        for (int bb = 0; bb < BATCH; ++bb) {
            const unsigned g = p + (unsigned)bb * NPOS;
            float4 f = feat[g];
            float4 o;
            o.x = f.x + t.x;
            o.y = f.y + t.y;
            o.z = f.z + t.z;
            o.w = f.w + t.w;
            out[g] = o;
        }
    }
}

extern "C" void kernel_launch(void* const* d_in, const int* in_sizes, int n_in,
                              void* d_out, int out_size)
{
    const float* feat = (const float*)d_in[0];  // [B, N, C]
    const float* pe   = (const float*)d_in[1];  // [X, Y, Z, C]
    const float* W    = (const float*)d_in[2];  // [C, C]
    const float* b    = (const float*)d_in[3];  // [C]

    proj_kernel<<<10, 1024>>>(pe, W, b);

    // 1184 blocks x 256 threads = 303,104 threads; ~7 positions per thread.
    add_kernel<<<1184, 256>>>((const float4*)feat, (float4*)d_out);
}

// round 3
// speedup vs baseline: 1.1654x; 1.1209x over previous
#include <cuda_runtime.h>

#define C    64
#define NX   64
#define NY   64
#define NZ   32
#define NVOX (NX*NY*NZ)      // 131072
#define NPOS (NVOX * (C/4))  // 2,097,152 float4 positions per batch plane
#define BATCH 8

// Projected separable tables: px[x][c], py[y][c], pz[z][c]
// (pz has bias and -2*proj(pe[0,0,0]) folded in). 16B aligned for float4.
__device__ __align__(16) float g_px[NX * C];
__device__ __align__(16) float g_py[NY * C];
__device__ __align__(16) float g_pz[NZ * C];

// ---------------------------------------------------------------------------
// Pass 1: project the 160 basis rows of pe through W^T.
// Separability of the reference pe (exact in fp32 up to rounding):
//   pe[x,y,z] = pe[x,0,0] + pe[0,y,0] + pe[0,0,z] - 2*pe[0,0,0]
// 20 blocks x 512 threads; block handles 8 rows, one output per thread.
// ---------------------------------------------------------------------------
__global__ void __launch_bounds__(512)
proj_kernel(const float* __restrict__ pe,
            const float* __restrict__ W,
            const float* __restrict__ b)
{
    __shared__ float sW[C * 65];   // padded -> conflict-free
    __shared__ float sR[8 * C];    // the 8 pe rows this block projects
    __shared__ float sR0[C];       // pe[0,0,0,:]

    const int tid  = threadIdx.x;
    const int rloc = tid >> 6;     // 0..7  local row
    const int c    = tid & 63;     // output channel

    // cooperative load of W [C,C]
    #pragma unroll
    for (int i = tid; i < C * C; i += 512)
        sW[(i >> 6) * 65 + (i & 63)] = W[i];

    const int row = blockIdx.x * 8 + rloc;    // 0..159
    const float* src;
    if (row < NX)            src = pe + (size_t)row * (NY * NZ * C);
    else if (row < NX + NY)  src = pe + (size_t)(row - NX) * (NZ * C);
    else                     src = pe + (size_t)(row - NX - NY) * C;

    sR[rloc * C + c] = src[c];
    if (tid < C) sR0[tid] = pe[tid];
    __syncthreads();

    float s = 0.f, s0 = 0.f;
    #pragma unroll
    for (int k = 0; k < C; ++k) {
        float w = sW[c * 65 + k];        // W[c,k]
        s  += sR[rloc * C + k] * w;
        s0 += sR0[k] * w;
    }

    if (row < NX) {
        g_px[row * C + c] = s;
    } else if (row < NX + NY) {
        g_py[(row - NX) * C + c] = s;
    } else {
        // fold bias and -2*proj(pe000) into the z table
        g_pz[(row - NX - NY) * C + c] = s + b[c] - 2.f * s0;
    }
}

// ---------------------------------------------------------------------------
// Pass 2: out[b,n,c] = feat[b,n,c] + (px[x]+py[y]+pz[z])[c]
// Exact-fit grid: one (n,c4) position per thread, no loop. All 8 batch-plane
// loads are issued before any store -> per-thread MLP = 8 (plus 3 table LDGs).
// ---------------------------------------------------------------------------
__global__ void __launch_bounds__(256)
add_kernel(const float4* __restrict__ feat,
           float4* __restrict__ out)
{
    const float4* __restrict__ px = reinterpret_cast<const float4*>(g_px);
    const float4* __restrict__ py = reinterpret_cast<const float4*>(g_py);
    const float4* __restrict__ pz = reinterpret_cast<const float4*>(g_pz);

    const unsigned p  = blockIdx.x * 256u + threadIdx.x;   // < NPOS by construction
    const unsigned c4 = p & 15u;           // float4 index within channel row
    const unsigned n  = p >> 4;
    const unsigned x  = n >> 11;           // n / (NY*NZ)
    const unsigned y  = (n >> 5) & 63u;    // (n / NZ) % NY
    const unsigned z  = n & 31u;           // n % NZ

    // 8 independent feature loads, front-batched
    float4 f[BATCH];
    #pragma unroll
    for (int bb = 0; bb < BATCH; ++bb)
        f[bb] = feat[p + (unsigned)bb * NPOS];

    const float4 a = __ldg(&px[(x << 4) | c4]);
    const float4 u = __ldg(&py[(y << 4) | c4]);
    const float4 v = __ldg(&pz[(z << 4) | c4]);

    float4 t;
    t.x = a.x + u.x + v.x;
    t.y = a.y + u.y + v.y;
    t.z = a.z + u.z + v.z;
    t.w = a.w + u.w + v.w;

    #pragma unroll
    for (int bb = 0; bb < BATCH; ++bb) {
        float4 o;
        o.x = f[bb].x + t.x;
        o.y = f[bb].y + t.y;
        o.z = f[bb].z + t.z;
        o.w = f[bb].w + t.w;
        out[p + (unsigned)bb * NPOS] = o;
    }
}

extern "C" void kernel_launch(void* const* d_in, const int* in_sizes, int n_in,
                              void* d_out, int out_size)
{
    const float* feat = (const float*)d_in[0];  // [B, N, C]
    const float* pe   = (const float*)d_in[1];  // [X, Y, Z, C]
    const float* W    = (const float*)d_in[2];  // [C, C]
    const float* b    = (const float*)d_in[3];  // [C]

    proj_kernel<<<20, 512>>>(pe, W, b);

    // NPOS / 256 = 8192 blocks, one float4 position per thread
    add_kernel<<<NPOS / 256, 256>>>((const float4*)feat, (float4*)d_out);
}

// round 4
// speedup vs baseline: 1.1960x; 1.0263x over previous
#include <cuda_runtime.h>

#define C    64
#define NX   64
#define NY   64
#define NZ   32
#define NVOX (NX*NY*NZ)      // 131072
#define NPOS (NVOX * (C/4))  // 2,097,152 float4 positions per batch plane
#define BATCH 8

// Projected separable tables: px[x][c], py[y][c], pz[z][c]
// (pz has bias and -2*proj(pe[0,0,0]) folded in). 16B aligned for float4.
__device__ __align__(16) float g_px[NX * C];
__device__ __align__(16) float g_py[NY * C];
__device__ __align__(16) float g_pz[NZ * C];

// ---------------------------------------------------------------------------
// Pass 1: project the 160 basis rows of pe through W^T.
// Separability of the reference pe (exact in fp32 up to rounding):
//   pe[x,y,z] = pe[x,0,0] + pe[0,y,0] + pe[0,0,z] - 2*pe[0,0,0]
// 40 blocks x 256 threads; block handles 4 rows, one output per thread.
// ---------------------------------------------------------------------------
__global__ void __launch_bounds__(256)
proj_kernel(const float* __restrict__ pe,
            const float* __restrict__ W,
            const float* __restrict__ b)
{
    __shared__ float sW[C * 65];   // padded -> conflict-free
    __shared__ float sR[4 * C];    // the 4 pe rows this block projects
    __shared__ float sR0[C];       // pe[0,0,0,:]

    const int tid  = threadIdx.x;
    const int rloc = tid >> 6;     // 0..3  local row
    const int c    = tid & 63;     // output channel

    // cooperative load of W [C,C]: 16 floats per thread
    #pragma unroll
    for (int i = tid; i < C * C; i += 256)
        sW[(i >> 6) * 65 + (i & 63)] = W[i];

    const int row = blockIdx.x * 4 + rloc;    // 0..159
    const float* src;
    if (row < NX)            src = pe + (size_t)row * (NY * NZ * C);
    else if (row < NX + NY)  src = pe + (size_t)(row - NX) * (NZ * C);
    else                     src = pe + (size_t)(row - NX - NY) * C;

    sR[rloc * C + c] = src[c];
    if (tid < C) sR0[tid] = pe[tid];
    __syncthreads();

    float s = 0.f, s0 = 0.f;
    #pragma unroll
    for (int k = 0; k < C; ++k) {
        float w = sW[c * 65 + k];        // W[c,k]
        s  += sR[rloc * C + k] * w;
        s0 += sR0[k] * w;
    }

    if (row < NX) {
        g_px[row * C + c] = s;
    } else if (row < NX + NY) {
        g_py[(row - NX) * C + c] = s;
    } else {
        // fold bias and -2*proj(pe000) into the z table
        g_pz[(row - NX - NY) * C + c] = s + b[c] - 2.f * s0;
    }
}

// ---------------------------------------------------------------------------
// Pass 2: out[b,n,c] = feat[b,n,c] + (px[x]+py[y]+pz[z])[c]
// Exact-fit grid: one (n,c4) position per thread. launch_bounds(256,2) grants
// enough registers to keep all 8 batch-plane loads live -> per-thread MLP=11.
// Streaming cache hints: data touched exactly once.
// ---------------------------------------------------------------------------
__global__ void __launch_bounds__(256, 2)
add_kernel(const float4* __restrict__ feat,
           float4* __restrict__ out)
{
    const float4* __restrict__ px = reinterpret_cast<const float4*>(g_px);
    const float4* __restrict__ py = reinterpret_cast<const float4*>(g_py);
    const float4* __restrict__ pz = reinterpret_cast<const float4*>(g_pz);

    const unsigned p  = blockIdx.x * 256u + threadIdx.x;   // < NPOS by construction
    const unsigned c4 = p & 15u;           // float4 index within channel row
    const unsigned n  = p >> 4;
    const unsigned x  = n >> 11;           // n / (NY*NZ)
    const unsigned y  = (n >> 5) & 63u;    // (n / NZ) % NY
    const unsigned z  = n & 31u;           // n % NZ

    // 8 independent feature loads, front-batched, evict-first (streaming)
    float4 f[BATCH];
    #pragma unroll
    for (int bb = 0; bb < BATCH; ++bb)
        f[bb] = __ldcs(&feat[p + (unsigned)bb * NPOS]);

    const float4 a = __ldg(&px[(x << 4) | c4]);
    const float4 u = __ldg(&py[(y << 4) | c4]);
    const float4 v = __ldg(&pz[(z << 4) | c4]);

    float4 t;
    t.x = a.x + u.x + v.x;
    t.y = a.y + u.y + v.y;
    t.z = a.z + u.z + v.z;
    t.w = a.w + u.w + v.w;

    #pragma unroll
    for (int bb = 0; bb < BATCH; ++bb) {
        float4 o;
        o.x = f[bb].x + t.x;
        o.y = f[bb].y + t.y;
        o.z = f[bb].z + t.z;
        o.w = f[bb].w + t.w;
        __stcs(&out[p + (unsigned)bb * NPOS], o);
    }
}

extern "C" void kernel_launch(void* const* d_in, const int* in_sizes, int n_in,
                              void* d_out, int out_size)
{
    const float* feat = (const float*)d_in[0];  // [B, N, C]
    const float* pe   = (const float*)d_in[1];  // [X, Y, Z, C]
    const float* W    = (const float*)d_in[2];  // [C, C]
    const float* b    = (const float*)d_in[3];  // [C]

    proj_kernel<<<40, 256>>>(pe, W, b);

    // NPOS / 256 = 8192 blocks, one float4 position per thread
    add_kernel<<<NPOS / 256, 256>>>((const float4*)feat, (float4*)d_out);
}